// round 2
// baseline (speedup 1.0000x reference)
#include <cuda_runtime.h>

#define N_NODES 8192
#define D 256
#define BM 64
#define BN 64
#define THREADS 256

// k-major tile strides (words)
#define QK_STRIDE 68   // 64 + 4 pad, 16B-aligned rows, 4-way-max store conflicts
#define PS_STRIDE 65

// Scratch for projected Q, K, V (device globals: no allocation allowed)
__device__ float g_Q[N_NODES * D];
__device__ float g_K[N_NODES * D];
__device__ float g_V[N_NODES * D];

// ---------------------------------------------------------------------------
// QKV projection: Out = X @ W  (three outputs selected by blockIdx.z)
// 64x64 output tile per CTA, 256 threads, 4x4 register microtile.
// ---------------------------------------------------------------------------
__global__ __launch_bounds__(THREADS)
void qkv_kernel(const float* __restrict__ X,
                const float* __restrict__ Wq,
                const float* __restrict__ Wk,
                const float* __restrict__ Wv) {
    const float* W = (blockIdx.z == 0) ? Wq : (blockIdx.z == 1) ? Wk : Wv;
    float* Out     = (blockIdx.z == 0) ? g_Q : (blockIdx.z == 1) ? g_K : g_V;

    __shared__ float Xs[32 * QK_STRIDE];  // [kk][r], transposed
    __shared__ float Ws[32 * QK_STRIDE];  // [kk][col]

    const int tid = threadIdx.x;
    const int tx = tid & 15;
    const int ty = tid >> 4;
    const int rowbase = blockIdx.x * 64;
    const int colbase = blockIdx.y * 64;

    float acc[4][4] = {};

    for (int k0 = 0; k0 < D; k0 += 32) {
        // X tile 64 rows x 32 k, store transposed [kk][r]
        for (int idx = tid; idx < 64 * 32; idx += THREADS) {
            int kk = idx & 31, r = idx >> 5;
            Xs[kk * QK_STRIDE + r] = X[(rowbase + r) * D + k0 + kk];
        }
        // W tile 32 k x 64 cols, natural [kk][col]
        for (int idx = tid; idx < 32 * 64; idx += THREADS) {
            int col = idx & 63, kk = idx >> 6;
            Ws[kk * QK_STRIDE + col] = W[(k0 + kk) * D + colbase + col];
        }
        __syncthreads();

        #pragma unroll 8
        for (int kk = 0; kk < 32; ++kk) {
            float4 xv = *reinterpret_cast<const float4*>(&Xs[kk * QK_STRIDE + 4 * ty]);
            float4 wv = *reinterpret_cast<const float4*>(&Ws[kk * QK_STRIDE + 4 * tx]);
            float xr[4] = {xv.x, xv.y, xv.z, xv.w};
            float wc[4] = {wv.x, wv.y, wv.z, wv.w};
            #pragma unroll
            for (int i = 0; i < 4; ++i)
                #pragma unroll
                for (int j = 0; j < 4; ++j)
                    acc[i][j] += xr[i] * wc[j];
        }
        __syncthreads();
    }

    #pragma unroll
    for (int i = 0; i < 4; ++i) {
        float4 o = make_float4(acc[i][0], acc[i][1], acc[i][2], acc[i][3]);
        *reinterpret_cast<float4*>(&Out[(rowbase + 4 * ty + i) * D + colbase + 4 * tx]) = o;
    }
}

// ---------------------------------------------------------------------------
// Fused masked attention with online softmax (flash-style).
// Each CTA: 64 query rows, loops over 128 chunks of 64 keys.
// Thread (tx=tid&15, ty=tid>>4): S microtile rows 4ty..+3, cols 4tx..+3;
// output dims {4tx + 64u : u<4} for its 4 rows.
// ---------------------------------------------------------------------------
__global__ __launch_bounds__(THREADS)
void attn_kernel(const int* __restrict__ A, float* __restrict__ Out) {
    extern __shared__ float sm[];
    float* Qs = sm;                       // [256][QK_STRIDE] k-major
    float* Ks = Qs + D * QK_STRIDE;       // [256][QK_STRIDE] k-major
    float* Vs = Ks + D * QK_STRIDE;       // [64][256] row-major
    float* Ps = Vs + BN * D;              // [64 c][PS_STRIDE] transposed P

    const int tid = threadIdx.x;
    const int tx = tid & 15;
    const int ty = tid >> 4;
    const int rowbase = blockIdx.x * BM;

    // Load Q tile transposed: Qs[kk][r]
    for (int idx = tid; idx < BM * D; idx += THREADS) {
        int kk = idx & (D - 1), r = idx >> 8;
        Qs[kk * QK_STRIDE + r] = g_Q[(rowbase + r) * D + kk];
    }

    float m_i[4], l_i[4];
    float acc[4][16];
    #pragma unroll
    for (int i = 0; i < 4; ++i) {
        m_i[i] = -1e30f;
        l_i[i] = 0.0f;
        #pragma unroll
        for (int u = 0; u < 16; ++u) acc[i][u] = 0.0f;
    }
    __syncthreads();

    for (int kb = 0; kb < N_NODES; kb += BN) {
        // K chunk transposed
        for (int idx = tid; idx < BN * D; idx += THREADS) {
            int kk = idx & (D - 1), r = idx >> 8;
            Ks[kk * QK_STRIDE + r] = g_K[(kb + r) * D + kk];
        }
        // V chunk row-major, float4
        for (int idx = tid; idx < BN * (D / 4); idx += THREADS) {
            int d4 = idx & 63, c = idx >> 6;
            reinterpret_cast<float4*>(Vs)[c * 64 + d4] =
                reinterpret_cast<const float4*>(g_V)[(kb + c) * 64 + d4];
        }
        __syncthreads();

        // ---- S = Q Kt (64x64 tile) ----
        float s[4][4] = {};
        #pragma unroll 4
        for (int kk = 0; kk < D; ++kk) {
            float4 qv = *reinterpret_cast<const float4*>(&Qs[kk * QK_STRIDE + 4 * ty]);
            float4 kv = *reinterpret_cast<const float4*>(&Ks[kk * QK_STRIDE + 4 * tx]);
            float qr[4] = {qv.x, qv.y, qv.z, qv.w};
            float kc[4] = {kv.x, kv.y, kv.z, kv.w};
            #pragma unroll
            for (int i = 0; i < 4; ++i)
                #pragma unroll
                for (int j = 0; j < 4; ++j)
                    s[i][j] += qr[i] * kc[j];
        }

        // ---- mask via adjacency (A==1 or diagonal) ----
        const int c0 = kb + 4 * tx;
        #pragma unroll
        for (int i = 0; i < 4; ++i) {
            int qrow = rowbase + 4 * ty + i;
            int4 a = *reinterpret_cast<const int4*>(&A[qrow * N_NODES + c0]);
            if (!(a.x | (qrow == c0 + 0))) s[i][0] = -1e30f;
            if (!(a.y | (qrow == c0 + 1))) s[i][1] = -1e30f;
            if (!(a.z | (qrow == c0 + 2))) s[i][2] = -1e30f;
            if (!(a.w | (qrow == c0 + 3))) s[i][3] = -1e30f;
        }

        // ---- online softmax (row reductions across the 16 tx lanes) ----
        #pragma unroll
        for (int i = 0; i < 4; ++i) {
            float mc = fmaxf(fmaxf(s[i][0], s[i][1]), fmaxf(s[i][2], s[i][3]));
            #pragma unroll
            for (int o = 8; o > 0; o >>= 1)
                mc = fmaxf(mc, __shfl_xor_sync(0xffffffffu, mc, o, 16));
            float m_new = fmaxf(m_i[i], mc);

            float p0 = __expf(s[i][0] - m_new);
            float p1 = __expf(s[i][1] - m_new);
            float p2 = __expf(s[i][2] - m_new);
            float p3 = __expf(s[i][3] - m_new);
            float rs = (p0 + p1) + (p2 + p3);
            #pragma unroll
            for (int o = 8; o > 0; o >>= 1)
                rs += __shfl_xor_sync(0xffffffffu, rs, o, 16);

            float scale = __expf(m_i[i] - m_new);  // 0 when m_i == -1e30 & m_new finite
            l_i[i] = l_i[i] * scale + rs;
            m_i[i] = m_new;
            #pragma unroll
            for (int u = 0; u < 16; ++u) acc[i][u] *= scale;

            // stash P transposed: Ps[c][r]
            int r = 4 * ty + i;
            Ps[(4 * tx + 0) * PS_STRIDE + r] = p0;
            Ps[(4 * tx + 1) * PS_STRIDE + r] = p1;
            Ps[(4 * tx + 2) * PS_STRIDE + r] = p2;
            Ps[(4 * tx + 3) * PS_STRIDE + r] = p3;
        }
        __syncthreads();

        // ---- acc += P @ V ----
        #pragma unroll 2
        for (int c = 0; c < BN; ++c) {
            float p[4];
            #pragma unroll
            for (int i = 0; i < 4; ++i) p[i] = Ps[c * PS_STRIDE + 4 * ty + i];
            const float4* vrow = reinterpret_cast<const float4*>(Vs + c * D);
            #pragma unroll
            for (int u = 0; u < 4; ++u) {
                float4 v = vrow[16 * u + tx];   // dims 64u + 4tx .. +3, conflict-free
                #pragma unroll
                for (int i = 0; i < 4; ++i) {
                    acc[i][4 * u + 0] += p[i] * v.x;
                    acc[i][4 * u + 1] += p[i] * v.y;
                    acc[i][4 * u + 2] += p[i] * v.z;
                    acc[i][4 * u + 3] += p[i] * v.w;
                }
            }
        }
        __syncthreads();
    }

    // ---- epilogue: Out = acc / l ----
    #pragma unroll
    for (int i = 0; i < 4; ++i) {
        float inv = 1.0f / l_i[i];
        int qrow = rowbase + 4 * ty + i;
        #pragma unroll
        for (int u = 0; u < 4; ++u) {
            float4 o = make_float4(acc[i][4 * u + 0] * inv, acc[i][4 * u + 1] * inv,
                                   acc[i][4 * u + 2] * inv, acc[i][4 * u + 3] * inv);
            *reinterpret_cast<float4*>(&Out[qrow * D + 64 * u + 4 * tx]) = o;
        }
    }
}

// ---------------------------------------------------------------------------
// kernel_launch: inputs (metadata order): X f32[8192,256], A i32[8192,8192],
// Wq f32[256,256], Wk f32[256,256], Wv f32[256,256]. Output f32[8192,256].
// ---------------------------------------------------------------------------
extern "C" void kernel_launch(void* const* d_in, const int* in_sizes, int n_in,
                              void* d_out, int out_size) {
    const float* X  = (const float*)d_in[0];
    const int*   A  = (const int*)d_in[1];
    const float* Wq = (const float*)d_in[2];
    const float* Wk = (const float*)d_in[3];
    const float* Wv = (const float*)d_in[4];
    float* Out = (float*)d_out;

    // QKV projections
    {
        dim3 grid(N_NODES / 64, D / 64, 3);
        qkv_kernel<<<grid, THREADS>>>(X, Wq, Wk, Wv);
    }

    // Fused masked attention
    {
        static int smem_set = 0;
        const int smem_bytes = (D * QK_STRIDE * 2 + BN * D + BN * PS_STRIDE) * (int)sizeof(float);
        if (!smem_set) {
            cudaFuncSetAttribute(attn_kernel, cudaFuncAttributeMaxDynamicSharedMemorySize,
                                 smem_bytes);
            smem_set = 1;
        }
        attn_kernel<<<N_NODES / BM, THREADS, smem_bytes>>>(A, Out);
    }
}

// round 6
// speedup vs baseline: 5.2630x; 5.2630x over previous
#include <cuda_runtime.h>
#include <cuda_bf16.h>
#include <cstdint>

#define NN 8192
#define DD 256
#define BM 64
#define BN 32
#define QK_STRIDE 68

// ---------------- device global scratch ----------------
__device__ __nv_bfloat16 g_Qhi[NN * DD], g_Qlo[NN * DD];
__device__ __nv_bfloat16 g_Khi[NN * DD], g_Klo[NN * DD];
__device__ __nv_bfloat16 g_Vhi[NN * DD], g_Vlo[NN * DD];
__device__ uint32_t g_mask[NN * (NN / 32)];   // bit c of word w: A[r][32w+c] || diag

// ---------------- helpers ----------------
__device__ __forceinline__ uint32_t smem_u32(const void* p) {
    uint32_t a;
    asm("{ .reg .u64 t; cvta.to.shared.u64 t, %1; cvt.u32.u64 %0, t; }" : "=r"(a) : "l"(p));
    return a;
}
// 16B-chunk XOR swizzle within 128B window; rows are 512B (256 bf16)
__device__ __forceinline__ uint32_t swz(int r, int c) {
    return (uint32_t)(r * 512 + ((((c ^ r) & 7) | (c & 24)) << 4));
}
__device__ __forceinline__ void ldm_x4(uint32_t a, uint32_t* r) {
    asm volatile("ldmatrix.sync.aligned.m8n8.x4.shared.b16 {%0,%1,%2,%3}, [%4];"
                 : "=r"(r[0]), "=r"(r[1]), "=r"(r[2]), "=r"(r[3]) : "r"(a));
}
__device__ __forceinline__ void ldm_x2(uint32_t a, uint32_t* r) {
    asm volatile("ldmatrix.sync.aligned.m8n8.x2.shared.b16 {%0,%1}, [%2];"
                 : "=r"(r[0]), "=r"(r[1]) : "r"(a));
}
__device__ __forceinline__ void ldm_x2t(uint32_t a, uint32_t* r) {
    asm volatile("ldmatrix.sync.aligned.m8n8.x2.trans.shared.b16 {%0,%1}, [%2];"
                 : "=r"(r[0]), "=r"(r[1]) : "r"(a));
}
__device__ __forceinline__ void mma_bf16(float* c, const uint32_t* a, const uint32_t* b) {
    asm volatile(
        "mma.sync.aligned.m16n8k16.row.col.f32.bf16.bf16.f32 "
        "{%0,%1,%2,%3},{%4,%5,%6,%7},{%8,%9},{%0,%1,%2,%3};"
        : "+f"(c[0]), "+f"(c[1]), "+f"(c[2]), "+f"(c[3])
        : "r"(a[0]), "r"(a[1]), "r"(a[2]), "r"(a[3]), "r"(b[0]), "r"(b[1]));
}
__device__ __forceinline__ void cpa16(uint32_t dst, const void* src) {
    asm volatile("cp.async.cg.shared.global [%0], [%1], 16;" :: "r"(dst), "l"(src));
}
template <int R>
__device__ __forceinline__ void cpa_tile(uint32_t sbase, const __nv_bfloat16* g,
                                         int row0, int tid) {
    const char* gp = (const char*)(g + (size_t)row0 * DD);
    #pragma unroll
    for (int t = 0; t < (R * 32) / 128; ++t) {
        int idx = tid + t * 128;
        int r = idx >> 5, c = idx & 31;
        cpa16(sbase + swz(r, c), gp + r * 512 + c * 16);
    }
}

union B4 { __nv_bfloat16 h[4]; uint2 u; };

// ---------------------------------------------------------------------------
// Pack adjacency to bitmask (diagonal OR-ed in). grid=NN, block=256.
// ---------------------------------------------------------------------------
__global__ __launch_bounds__(256)
void pack_mask_kernel(const int* __restrict__ A) {
    const int row = blockIdx.x;
    const int lane = threadIdx.x & 31, w0 = threadIdx.x >> 5;
    for (int w = w0; w < NN / 32; w += 8) {
        int col = w * 32 + lane;
        bool keep = (A[(size_t)row * NN + col] != 0) || (row == col);
        uint32_t bits = __ballot_sync(0xffffffffu, keep);
        if (lane == 0) g_mask[(size_t)row * (NN / 32) + w] = bits;
    }
}

// ---------------------------------------------------------------------------
// QKV projection -> bf16 hi/lo directly. grid (128,4,3), block 256.
// ---------------------------------------------------------------------------
__global__ __launch_bounds__(256)
void qkv_kernel(const float* __restrict__ X, const float* __restrict__ Wq,
                const float* __restrict__ Wk, const float* __restrict__ Wv) {
    const int z = blockIdx.z;
    const float* W = (z == 0) ? Wq : (z == 1) ? Wk : Wv;
    __nv_bfloat16* Oh = (z == 0) ? g_Qhi : (z == 1) ? g_Khi : g_Vhi;
    __nv_bfloat16* Ol = (z == 0) ? g_Qlo : (z == 1) ? g_Klo : g_Vlo;

    __shared__ float Xs[32 * QK_STRIDE];
    __shared__ float Ws[32 * QK_STRIDE];
    const int tid = threadIdx.x, tx = tid & 15, ty = tid >> 4;
    const int rowbase = blockIdx.x * 64, colbase = blockIdx.y * 64;
    float acc[4][4] = {};

    for (int k0 = 0; k0 < DD; k0 += 32) {
        for (int idx = tid; idx < 64 * 32; idx += 256) {
            int kk = idx & 31, r = idx >> 5;
            Xs[kk * QK_STRIDE + r] = X[(rowbase + r) * DD + k0 + kk];
        }
        for (int idx = tid; idx < 32 * 64; idx += 256) {
            int col = idx & 63, kk = idx >> 6;
            Ws[kk * QK_STRIDE + col] = W[(k0 + kk) * DD + colbase + col];
        }
        __syncthreads();
        #pragma unroll 8
        for (int kk = 0; kk < 32; ++kk) {
            float4 xv = *reinterpret_cast<const float4*>(&Xs[kk * QK_STRIDE + 4 * ty]);
            float4 wv = *reinterpret_cast<const float4*>(&Ws[kk * QK_STRIDE + 4 * tx]);
            float xr[4] = {xv.x, xv.y, xv.z, xv.w};
            float wc[4] = {wv.x, wv.y, wv.z, wv.w};
            #pragma unroll
            for (int i = 0; i < 4; ++i)
                #pragma unroll
                for (int j = 0; j < 4; ++j) acc[i][j] += xr[i] * wc[j];
        }
        __syncthreads();
    }
    #pragma unroll
    for (int i = 0; i < 4; ++i) {
        int row = rowbase + 4 * ty + i, col = colbase + 4 * tx;
        B4 hh, ll;
        #pragma unroll
        for (int j = 0; j < 4; ++j) {
            float v = acc[i][j];
            __nv_bfloat16 h = __float2bfloat16(v);
            hh.h[j] = h;
            ll.h[j] = __float2bfloat16(v - __bfloat162float(h));
        }
        *reinterpret_cast<uint2*>(&Oh[(size_t)row * DD + col]) = hh.u;
        *reinterpret_cast<uint2*>(&Ol[(size_t)row * DD + col]) = ll.u;
    }
}

// ---------------------------------------------------------------------------
// Single-pass flash attention, bf16x3 on mma.sync tensor cores.
// grid 128, block 128 (4 warps; warp owns 16 rows, full D=256).
// smem: Qhi 32K | Qlo 32K | 2 x {Khi 16K | Klo 16K | Vhi 16K | Vlo 16K}
// ---------------------------------------------------------------------------
__global__ __launch_bounds__(128, 1)
void attn_kernel(float* __restrict__ Out) {
    extern __shared__ char smem[];
    const int tid = threadIdx.x, warp = tid >> 5, lane = tid & 31;
    const int g = lane >> 2, t4 = lane & 3;
    const int rowbase = blockIdx.x * BM;

    const uint32_t sbase = smem_u32(smem);
    const uint32_t sQH = sbase, sQL = sbase + 32768;

    // prologue loads
    cpa_tile<BM>(sQH, g_Qhi, rowbase, tid);
    cpa_tile<BM>(sQL, g_Qlo, rowbase, tid);
    {
        uint32_t B0 = sbase + 65536;
        cpa_tile<BN>(B0, g_Khi, 0, tid);
        cpa_tile<BN>(B0 + 16384, g_Klo, 0, tid);
        cpa_tile<BN>(B0 + 32768, g_Vhi, 0, tid);
        cpa_tile<BN>(B0 + 49152, g_Vlo, 0, tid);
    }
    asm volatile("cp.async.commit_group;");

    float O[32][4];
    #pragma unroll
    for (int dt = 0; dt < 32; ++dt) {
        O[dt][0] = 0.f; O[dt][1] = 0.f; O[dt][2] = 0.f; O[dt][3] = 0.f;
    }
    float m0 = -1e30f, m1 = -1e30f, l0 = 0.f, l1 = 0.f;

    const int rg0 = rowbase + 16 * warp + g;   // rows for C-frag halves
    const int rg1 = rg0 + 8;
    const uint32_t* mrow0 = g_mask + (size_t)rg0 * (NN / 32);
    const uint32_t* mrow1 = g_mask + (size_t)rg1 * (NN / 32);

    const int qr = 16 * warp + (lane & 15);
    const int kr = lane & 7;
    const int kcsel = (lane >> 3) & 1;
    const int qcsel = lane >> 4;

    for (int b = 0; b < NN / BN; ++b) {
        const int cur = b & 1;
        const uint32_t KB = sbase + 65536 + cur * 65536;
        if (b + 1 < NN / BN) {
            const uint32_t NB_ = sbase + 65536 + (cur ^ 1) * 65536;
            const int nk = (b + 1) * BN;
            cpa_tile<BN>(NB_, g_Khi, nk, tid);
            cpa_tile<BN>(NB_ + 16384, g_Klo, nk, tid);
            cpa_tile<BN>(NB_ + 32768, g_Vhi, nk, tid);
            cpa_tile<BN>(NB_ + 49152, g_Vlo, nk, tid);
            asm volatile("cp.async.commit_group;");
            asm volatile("cp.async.wait_group 1;");
        } else {
            asm volatile("cp.async.wait_group 0;");
        }
        __syncthreads();

        const uint32_t KH = KB, KL = KB + 16384, VH = KB + 32768, VL = KB + 49152;

        // ---- S = Q K^T (16 x 32 per warp), bf16x3 ----
        float S[4][4] = {};
        #pragma unroll 4
        for (int kk = 0; kk < 16; ++kk) {
            uint32_t aH[4], aL[4];
            int qc = 2 * kk + qcsel;
            ldm_x4(sQH + swz(qr, qc), aH);
            ldm_x4(sQL + swz(qr, qc), aL);
            int kc = 2 * kk + kcsel;
            #pragma unroll
            for (int j = 0; j < 4; ++j) {
                uint32_t bH[2], bL[2];
                ldm_x2(KH + swz(8 * j + kr, kc), bH);
                ldm_x2(KL + swz(8 * j + kr, kc), bL);
                mma_bf16(S[j], aH, bH);
                mma_bf16(S[j], aL, bH);
                mma_bf16(S[j], aH, bL);
            }
        }

        // ---- mask + online softmax ----
        const uint32_t mw0 = mrow0[b], mw1 = mrow1[b];
        float pv[4][4];
        float mt0 = -1e30f, mt1 = -1e30f;
        #pragma unroll
        for (int j = 0; j < 4; ++j)
            #pragma unroll
            for (int e = 0; e < 2; ++e) {
                int bit = 8 * j + 2 * t4 + e;
                float s0 = ((mw0 >> bit) & 1u) ? S[j][e] : -1e30f;
                float s1 = ((mw1 >> bit) & 1u) ? S[j][2 + e] : -1e30f;
                pv[j][e] = s0; pv[j][2 + e] = s1;
                mt0 = fmaxf(mt0, s0); mt1 = fmaxf(mt1, s1);
            }
        mt0 = fmaxf(mt0, __shfl_xor_sync(0xffffffffu, mt0, 1));
        mt0 = fmaxf(mt0, __shfl_xor_sync(0xffffffffu, mt0, 2));
        mt1 = fmaxf(mt1, __shfl_xor_sync(0xffffffffu, mt1, 1));
        mt1 = fmaxf(mt1, __shfl_xor_sync(0xffffffffu, mt1, 2));

        const float mn0 = fmaxf(m0, mt0), mn1 = fmaxf(m1, mt1);
        const float sc0 = __expf(m0 - mn0), sc1 = __expf(m1 - mn1);
        float rs0 = 0.f, rs1 = 0.f;
        #pragma unroll
        for (int j = 0; j < 4; ++j)
            #pragma unroll
            for (int e = 0; e < 2; ++e) {
                int bit = 8 * j + 2 * t4 + e;
                float p0 = ((mw0 >> bit) & 1u) ? __expf(pv[j][e] - mn0) : 0.f;
                float p1 = ((mw1 >> bit) & 1u) ? __expf(pv[j][2 + e] - mn1) : 0.f;
                pv[j][e] = p0; pv[j][2 + e] = p1;
                rs0 += p0; rs1 += p1;
            }
        rs0 += __shfl_xor_sync(0xffffffffu, rs0, 1);
        rs0 += __shfl_xor_sync(0xffffffffu, rs0, 2);
        rs1 += __shfl_xor_sync(0xffffffffu, rs1, 1);
        rs1 += __shfl_xor_sync(0xffffffffu, rs1, 2);
        l0 = l0 * sc0 + rs0;
        l1 = l1 * sc1 + rs1;
        m0 = mn0; m1 = mn1;

        if (__ballot_sync(0xffffffffu, (sc0 != 1.f) || (sc1 != 1.f))) {
            #pragma unroll
            for (int dt = 0; dt < 32; ++dt) {
                O[dt][0] *= sc0; O[dt][1] *= sc0;
                O[dt][2] *= sc1; O[dt][3] *= sc1;
            }
        }

        // ---- P -> bf16 hi/lo A-fragments (in registers) ----
        uint32_t Ph[4][2], Pl[4][2];
        #pragma unroll
        for (int j = 0; j < 4; ++j) {
            __nv_bfloat16 h0 = __float2bfloat16(pv[j][0]);
            __nv_bfloat16 h1 = __float2bfloat16(pv[j][1]);
            __nv_bfloat162 hh = __halves2bfloat162(h0, h1);
            __nv_bfloat162 ll = __floats2bfloat162_rn(
                pv[j][0] - __bfloat162float(h0), pv[j][1] - __bfloat162float(h1));
            Ph[j][0] = *reinterpret_cast<uint32_t*>(&hh);
            Pl[j][0] = *reinterpret_cast<uint32_t*>(&ll);
            __nv_bfloat16 h2 = __float2bfloat16(pv[j][2]);
            __nv_bfloat16 h3 = __float2bfloat16(pv[j][3]);
            __nv_bfloat162 hh2 = __halves2bfloat162(h2, h3);
            __nv_bfloat162 ll2 = __floats2bfloat162_rn(
                pv[j][2] - __bfloat162float(h2), pv[j][3] - __bfloat162float(h3));
            Ph[j][1] = *reinterpret_cast<uint32_t*>(&hh2);
            Pl[j][1] = *reinterpret_cast<uint32_t*>(&ll2);
        }

        // ---- O += P V  (V via ldmatrix.trans), bf16x3 ----
        #pragma unroll
        for (int kp = 0; kp < 2; ++kp) {
            uint32_t aH[4] = {Ph[2 * kp][0], Ph[2 * kp][1], Ph[2 * kp + 1][0], Ph[2 * kp + 1][1]};
            uint32_t aL[4] = {Pl[2 * kp][0], Pl[2 * kp][1], Pl[2 * kp + 1][0], Pl[2 * kp + 1][1]};
            const int vr = 16 * kp + (lane & 15);
            #pragma unroll
            for (int dt = 0; dt < 32; ++dt) {
                uint32_t bH[2], bL[2];
                ldm_x2t(VH + swz(vr, dt), bH);
                ldm_x2t(VL + swz(vr, dt), bL);
                mma_bf16(O[dt], aH, bH);
                mma_bf16(O[dt], aL, bH);
                mma_bf16(O[dt], aH, bL);
            }
        }
        __syncthreads();   // all warps done with buf cur before next prefetch overwrites it
    }

    // ---- epilogue: normalize + store ----
    const float i0 = 1.f / l0, i1 = 1.f / l1;
    float2* o0 = reinterpret_cast<float2*>(Out + (size_t)rg0 * DD);
    float2* o1 = reinterpret_cast<float2*>(Out + (size_t)rg1 * DD);
    #pragma unroll
    for (int dt = 0; dt < 32; ++dt) {
        o0[4 * dt + t4] = make_float2(O[dt][0] * i0, O[dt][1] * i0);
        o1[4 * dt + t4] = make_float2(O[dt][2] * i1, O[dt][3] * i1);
    }
}

// ---------------------------------------------------------------------------
extern "C" void kernel_launch(void* const* d_in, const int* in_sizes, int n_in,
                              void* d_out, int out_size) {
    const float* X  = (const float*)d_in[0];
    const int*   A  = (const int*)d_in[1];
    const float* Wq = (const float*)d_in[2];
    const float* Wk = (const float*)d_in[3];
    const float* Wv = (const float*)d_in[4];
    float* Out = (float*)d_out;

    static int attr_set = 0;
    const int smem_bytes = 196608;   // 64K Q + 2 x 64K KV buffers
    if (!attr_set) {
        cudaFuncSetAttribute(attn_kernel, cudaFuncAttributeMaxDynamicSharedMemorySize,
                             smem_bytes);
        attr_set = 1;
    }

    pack_mask_kernel<<<NN, 256>>>(A);
    qkv_kernel<<<dim3(NN / 64, DD / 64, 3), 256>>>(X, Wq, Wk, Wv);
    attn_kernel<<<NN / BM, 128, smem_bytes>>>(Out);
}

// round 7
// speedup vs baseline: 6.2613x; 1.1897x over previous
#include <cuda_runtime.h>
#include <cuda_bf16.h>
#include <cstdint>

#define NN 8192
#define DD 256
#define BM 64
#define BN 32
#define QK_STRIDE 68

// ---------------- device global scratch ----------------
__device__ __nv_bfloat16 g_Qhi[NN * DD], g_Qlo[NN * DD];
__device__ __nv_bfloat16 g_Khi[NN * DD], g_Klo[NN * DD];
__device__ __nv_bfloat16 g_Vhi[NN * DD], g_Vlo[NN * DD];
__device__ uint32_t g_mask[NN * (NN / 32)];

// ---------------- helpers ----------------
__device__ __forceinline__ uint32_t smem_u32(const void* p) {
    uint32_t a;
    asm("{ .reg .u64 t; cvta.to.shared.u64 t, %1; cvt.u32.u64 %0, t; }" : "=r"(a) : "l"(p));
    return a;
}
// 16B-chunk XOR swizzle within 128B window; rows are 512B (256 bf16)
__device__ __forceinline__ uint32_t swz(int r, int c) {
    return (uint32_t)(r * 512 + ((((c ^ r) & 7) | (c & 24)) << 4));
}
__device__ __forceinline__ void ldm_x4(uint32_t a, uint32_t* r) {
    asm volatile("ldmatrix.sync.aligned.m8n8.x4.shared.b16 {%0,%1,%2,%3}, [%4];"
                 : "=r"(r[0]), "=r"(r[1]), "=r"(r[2]), "=r"(r[3]) : "r"(a));
}
__device__ __forceinline__ void ldm_x4t(uint32_t a, uint32_t* r) {
    asm volatile("ldmatrix.sync.aligned.m8n8.x4.trans.shared.b16 {%0,%1,%2,%3}, [%4];"
                 : "=r"(r[0]), "=r"(r[1]), "=r"(r[2]), "=r"(r[3]) : "r"(a));
}
__device__ __forceinline__ void mma_bf16(float* c, const uint32_t* a, const uint32_t* b) {
    asm volatile(
        "mma.sync.aligned.m16n8k16.row.col.f32.bf16.bf16.f32 "
        "{%0,%1,%2,%3},{%4,%5,%6,%7},{%8,%9},{%0,%1,%2,%3};"
        : "+f"(c[0]), "+f"(c[1]), "+f"(c[2]), "+f"(c[3])
        : "r"(a[0]), "r"(a[1]), "r"(a[2]), "r"(a[3]), "r"(b[0]), "r"(b[1]));
}
__device__ __forceinline__ void cpa16(uint32_t dst, const void* src) {
    asm volatile("cp.async.cg.shared.global [%0], [%1], 16;" :: "r"(dst), "l"(src));
}
#define CPA_COMMIT() asm volatile("cp.async.commit_group;")
#define CPA_WAIT0() asm volatile("cp.async.wait_group 0;")
#define CPA_WAIT1() asm volatile("cp.async.wait_group 1;")
#define GBAR(id) asm volatile("bar.sync %0, 128;" :: "r"(id) : "memory")

// tile loader: R rows x 256 bf16, NT participating threads (ltid in [0,NT))
template <int R, int NT>
__device__ __forceinline__ void cpa_tile(uint32_t sbase, const __nv_bfloat16* g,
                                         int row0, int ltid) {
    const char* gp = (const char*)(g + (size_t)row0 * DD);
    #pragma unroll
    for (int t = 0; t < (R * 32) / NT; ++t) {
        int idx = ltid + t * NT;
        int r = idx >> 5, c = idx & 31;
        cpa16(sbase + swz(r, c), gp + r * 512 + c * 16);
    }
}

union B4 { __nv_bfloat16 h[4]; uint2 u; };

// ---------------------------------------------------------------------------
// Pack adjacency to bitmask (int4 loads, ~DRAM peak). grid=NN, block=256.
// ---------------------------------------------------------------------------
__global__ __launch_bounds__(256)
void pack_mask_kernel(const int* __restrict__ A) {
    const int row = blockIdx.x;
    const int lane = threadIdx.x & 31, w = threadIdx.x >> 5;
    const int4* arow = (const int4*)(A + (size_t)row * NN);
    #pragma unroll
    for (int it = 0; it < 8; ++it) {
        int blk = w + it * 8;               // 128-col chunk index (0..63)
        int col0 = blk * 128 + lane * 4;
        int4 v = arow[blk * 32 + lane];
        uint32_t nib = (v.x != 0 ? 1u : 0u) | (v.y != 0 ? 2u : 0u) |
                       (v.z != 0 ? 4u : 0u) | (v.w != 0 ? 8u : 0u);
        uint32_t d = (uint32_t)(row - col0);
        if (d < 4u) nib |= 1u << d;
        uint32_t bits = nib << (4 * (lane & 7));
        bits |= __shfl_xor_sync(0xffffffffu, bits, 1);
        bits |= __shfl_xor_sync(0xffffffffu, bits, 2);
        bits |= __shfl_xor_sync(0xffffffffu, bits, 4);
        if ((lane & 7) == 0)
            g_mask[(size_t)row * (NN / 32) + blk * 4 + (lane >> 3)] = bits;
    }
}

// ---------------------------------------------------------------------------
// QKV projection -> bf16 hi/lo. grid (128,4,3), block 256.
// ---------------------------------------------------------------------------
__global__ __launch_bounds__(256)
void qkv_kernel(const float* __restrict__ X, const float* __restrict__ Wq,
                const float* __restrict__ Wk, const float* __restrict__ Wv) {
    const int z = blockIdx.z;
    const float* W = (z == 0) ? Wq : (z == 1) ? Wk : Wv;
    __nv_bfloat16* Oh = (z == 0) ? g_Qhi : (z == 1) ? g_Khi : g_Vhi;
    __nv_bfloat16* Ol = (z == 0) ? g_Qlo : (z == 1) ? g_Klo : g_Vlo;

    __shared__ float Xs[32 * QK_STRIDE];
    __shared__ float Ws[32 * QK_STRIDE];
    const int tid = threadIdx.x, tx = tid & 15, ty = tid >> 4;
    const int rowbase = blockIdx.x * 64, colbase = blockIdx.y * 64;
    float acc[4][4] = {};

    for (int k0 = 0; k0 < DD; k0 += 32) {
        for (int idx = tid; idx < 64 * 32; idx += 256) {
            int kk = idx & 31, r = idx >> 5;
            Xs[kk * QK_STRIDE + r] = X[(rowbase + r) * DD + k0 + kk];
        }
        for (int idx = tid; idx < 32 * 64; idx += 256) {
            int col = idx & 63, kk = idx >> 6;
            Ws[kk * QK_STRIDE + col] = W[(k0 + kk) * DD + colbase + col];
        }
        __syncthreads();
        #pragma unroll 8
        for (int kk = 0; kk < 32; ++kk) {
            float4 xv = *reinterpret_cast<const float4*>(&Xs[kk * QK_STRIDE + 4 * ty]);
            float4 wv = *reinterpret_cast<const float4*>(&Ws[kk * QK_STRIDE + 4 * tx]);
            float xr[4] = {xv.x, xv.y, xv.z, xv.w};
            float wc[4] = {wv.x, wv.y, wv.z, wv.w};
            #pragma unroll
            for (int i = 0; i < 4; ++i)
                #pragma unroll
                for (int j = 0; j < 4; ++j) acc[i][j] += xr[i] * wc[j];
        }
        __syncthreads();
    }
    #pragma unroll
    for (int i = 0; i < 4; ++i) {
        int row = rowbase + 4 * ty + i, col = colbase + 4 * tx;
        B4 hh, ll;
        #pragma unroll
        for (int j = 0; j < 4; ++j) {
            float v = acc[i][j];
            __nv_bfloat16 h = __float2bfloat16(v);
            hh.h[j] = h;
            ll.h[j] = __float2bfloat16(v - __bfloat162float(h));
        }
        *reinterpret_cast<uint2*>(&Oh[(size_t)row * DD + col]) = hh.u;
        *reinterpret_cast<uint2*>(&Ol[(size_t)row * DD + col]) = ll.u;
    }
}

// ---------------------------------------------------------------------------
// Flash attention, bf16x3 mma.sync, 8 warps in 2 ping-pong groups.
// Group g (warps 4g..4g+3) handles key blocks b = 2i+g with private m/l/O.
// smem: Q hi/lo 64K | group0 K/V 64K | group1 K/V 64K  = 192K
// ---------------------------------------------------------------------------
__global__ __launch_bounds__(256, 1)
void attn_kernel(float* __restrict__ Out) {
    extern __shared__ char smem[];
    const int tid = threadIdx.x, warp = tid >> 5, lane = tid & 31;
    const int grp = warp >> 2, wg = warp & 3, ltid = tid & 127;
    const int g = lane >> 2, t4 = lane & 3;
    const int rowbase = blockIdx.x * BM;

    const uint32_t sbase = smem_u32(smem);
    const uint32_t sQH = sbase, sQL = sbase + 32768;
    const uint32_t KB = sbase + 65536 + grp * 65536;
    const uint32_t KH = KB, KL = KB + 16384, VH = KB + 32768, VL = KB + 49152;
    const int barid = grp + 1;

    // prologue: Q (all threads) + this group's first K
    cpa_tile<BM, 256>(sQH, g_Qhi, rowbase, tid);
    cpa_tile<BM, 256>(sQL, g_Qlo, rowbase, tid);
    cpa_tile<BN, 128>(KH, g_Khi, grp * BN, ltid);
    cpa_tile<BN, 128>(KL, g_Klo, grp * BN, ltid);
    CPA_COMMIT();

    float O[32][4];
    #pragma unroll
    for (int dt = 0; dt < 32; ++dt) {
        O[dt][0] = 0.f; O[dt][1] = 0.f; O[dt][2] = 0.f; O[dt][3] = 0.f;
    }
    float m0 = -1e30f, m1 = -1e30f, l0 = 0.f, l1 = 0.f;

    const int rg0 = rowbase + 16 * wg + g;
    const int rg1 = rg0 + 8;
    const uint32_t* mrow0 = g_mask + (size_t)rg0 * (NN / 32);
    const uint32_t* mrow1 = g_mask + (size_t)rg1 * (NN / 32);

    const int qr = 16 * wg + (lane & 15);
    const int qcsel = lane >> 4;
    // K x4 address: matrices (j0,kc0)(j0,kc1)(j1,kc0)(j1,kc1)
    const int k_j_half = lane >> 4;          // 0/1 within jj pair
    const int k_kcsel = (lane >> 3) & 1;
    const int kr8 = lane & 7;
    // V x4t address: two d-tiles per op
    const int v_dtsel = lane >> 4;
    const int vlane = lane & 15;

    const int NBLK = NN / BN;   // 256
    for (int i = 0; i < NBLK / 2; ++i) {
        const int b = 2 * i + grp;

        // V of this block (overlaps S compute)
        cpa_tile<BN, 128>(VH, g_Vhi, b * BN, ltid);
        cpa_tile<BN, 128>(VL, g_Vlo, b * BN, ltid);
        CPA_COMMIT();
        CPA_WAIT1();               // K[b] (and Q) landed
        GBAR(barid);

        // ---- S = Q K^T (16x32 per warp), bf16x3, x4 ldmatrix ----
        float S[4][4] = {};
        #pragma unroll 4
        for (int kk = 0; kk < 16; ++kk) {
            uint32_t aH[4], aL[4];
            ldm_x4(sQH + swz(qr, 2 * kk + qcsel), aH);
            ldm_x4(sQL + swz(qr, 2 * kk + qcsel), aL);
            #pragma unroll
            for (int jjp = 0; jjp < 2; ++jjp) {
                int krow = 8 * (2 * jjp + k_j_half) + kr8;
                int kc = 2 * kk + k_kcsel;
                uint32_t bH[4], bL[4];
                ldm_x4(KH + swz(krow, kc), bH);
                ldm_x4(KL + swz(krow, kc), bL);
                mma_bf16(S[2 * jjp], aH, bH);
                mma_bf16(S[2 * jjp], aL, bH);
                mma_bf16(S[2 * jjp], aH, bL);
                mma_bf16(S[2 * jjp + 1], aH, bH + 2);
                mma_bf16(S[2 * jjp + 1], aL, bH + 2);
                mma_bf16(S[2 * jjp + 1], aH, bL + 2);
            }
        }
        GBAR(barid);               // group done reading K[b]

        // prefetch K for this group's next block (overlaps PV)
        if (i + 1 < NBLK / 2) {
            cpa_tile<BN, 128>(KH, g_Khi, (b + 2) * BN, ltid);
            cpa_tile<BN, 128>(KL, g_Klo, (b + 2) * BN, ltid);
            CPA_COMMIT();
            CPA_WAIT1();           // V[b] landed (K still in flight)
        } else {
            CPA_WAIT0();
        }

        // ---- mask + online softmax ----
        const uint32_t mw0 = mrow0[b], mw1 = mrow1[b];
        float pv[4][4];
        float mt0 = -1e30f, mt1 = -1e30f;
        #pragma unroll
        for (int j = 0; j < 4; ++j)
            #pragma unroll
            for (int e = 0; e < 2; ++e) {
                int bit = 8 * j + 2 * t4 + e;
                float s0 = ((mw0 >> bit) & 1u) ? S[j][e] : -1e30f;
                float s1 = ((mw1 >> bit) & 1u) ? S[j][2 + e] : -1e30f;
                pv[j][e] = s0; pv[j][2 + e] = s1;
                mt0 = fmaxf(mt0, s0); mt1 = fmaxf(mt1, s1);
            }
        mt0 = fmaxf(mt0, __shfl_xor_sync(0xffffffffu, mt0, 1));
        mt0 = fmaxf(mt0, __shfl_xor_sync(0xffffffffu, mt0, 2));
        mt1 = fmaxf(mt1, __shfl_xor_sync(0xffffffffu, mt1, 1));
        mt1 = fmaxf(mt1, __shfl_xor_sync(0xffffffffu, mt1, 2));

        const float mn0 = fmaxf(m0, mt0), mn1 = fmaxf(m1, mt1);
        const float sc0 = __expf(m0 - mn0), sc1 = __expf(m1 - mn1);
        float rs0 = 0.f, rs1 = 0.f;
        #pragma unroll
        for (int j = 0; j < 4; ++j)
            #pragma unroll
            for (int e = 0; e < 2; ++e) {
                int bit = 8 * j + 2 * t4 + e;
                float p0 = ((mw0 >> bit) & 1u) ? __expf(pv[j][e] - mn0) : 0.f;
                float p1 = ((mw1 >> bit) & 1u) ? __expf(pv[j][2 + e] - mn1) : 0.f;
                pv[j][e] = p0; pv[j][2 + e] = p1;
                rs0 += p0; rs1 += p1;
            }
        rs0 += __shfl_xor_sync(0xffffffffu, rs0, 1);
        rs0 += __shfl_xor_sync(0xffffffffu, rs0, 2);
        rs1 += __shfl_xor_sync(0xffffffffu, rs1, 1);
        rs1 += __shfl_xor_sync(0xffffffffu, rs1, 2);
        l0 = l0 * sc0 + rs0;
        l1 = l1 * sc1 + rs1;
        m0 = mn0; m1 = mn1;

        if (__ballot_sync(0xffffffffu, (sc0 != 1.f) || (sc1 != 1.f))) {
            #pragma unroll
            for (int dt = 0; dt < 32; ++dt) {
                O[dt][0] *= sc0; O[dt][1] *= sc0;
                O[dt][2] *= sc1; O[dt][3] *= sc1;
            }
        }

        // ---- P -> bf16 hi/lo A-fragments ----
        uint32_t Ph[4][2], Pl[4][2];
        #pragma unroll
        for (int j = 0; j < 4; ++j) {
            __nv_bfloat16 h0 = __float2bfloat16(pv[j][0]);
            __nv_bfloat16 h1 = __float2bfloat16(pv[j][1]);
            __nv_bfloat162 hh = __halves2bfloat162(h0, h1);
            __nv_bfloat162 ll = __floats2bfloat162_rn(
                pv[j][0] - __bfloat162float(h0), pv[j][1] - __bfloat162float(h1));
            Ph[j][0] = *reinterpret_cast<uint32_t*>(&hh);
            Pl[j][0] = *reinterpret_cast<uint32_t*>(&ll);
            __nv_bfloat16 h2 = __float2bfloat16(pv[j][2]);
            __nv_bfloat16 h3 = __float2bfloat16(pv[j][3]);
            __nv_bfloat162 hh2 = __halves2bfloat162(h2, h3);
            __nv_bfloat162 ll2 = __floats2bfloat162_rn(
                pv[j][2] - __bfloat162float(h2), pv[j][3] - __bfloat162float(h3));
            Ph[j][1] = *reinterpret_cast<uint32_t*>(&hh2);
            Pl[j][1] = *reinterpret_cast<uint32_t*>(&ll2);
        }

        GBAR(barid);               // V[b] visible to whole group

        // ---- O += P V (x4 trans ldmatrix: 2 d-tiles per op) ----
        #pragma unroll
        for (int kp = 0; kp < 2; ++kp) {
            uint32_t aH[4] = {Ph[2 * kp][0], Ph[2 * kp][1], Ph[2 * kp + 1][0], Ph[2 * kp + 1][1]};
            uint32_t aL[4] = {Pl[2 * kp][0], Pl[2 * kp][1], Pl[2 * kp + 1][0], Pl[2 * kp + 1][1]};
            const int vr = 16 * kp + vlane;
            #pragma unroll
            for (int dtp = 0; dtp < 16; ++dtp) {
                int vc = 2 * dtp + v_dtsel;
                uint32_t bH[4], bL[4];
                ldm_x4t(VH + swz(vr, vc), bH);
                ldm_x4t(VL + swz(vr, vc), bL);
                mma_bf16(O[2 * dtp], aH, bH);
                mma_bf16(O[2 * dtp], aL, bH);
                mma_bf16(O[2 * dtp], aH, bL);
                mma_bf16(O[2 * dtp + 1], aH, bH + 2);
                mma_bf16(O[2 * dtp + 1], aL, bH + 2);
                mma_bf16(O[2 * dtp + 1], aH, bL + 2);
            }
        }
        GBAR(barid);               // group done reading V[b] before next overwrite
    }

    // ---- merge groups ----
    __syncthreads();
    float* Os = reinterpret_cast<float*>(smem + 65536);   // [64][264] padded
    float* ml = reinterpret_cast<float*>(smem + 133120);  // m[64], l[64]
    const int r0l = 16 * wg + g, r1l = r0l + 8;
    if (grp == 1) {
        #pragma unroll
        for (int dt = 0; dt < 32; ++dt) {
            int c = 8 * dt + 2 * t4;
            Os[r0l * 264 + c] = O[dt][0]; Os[r0l * 264 + c + 1] = O[dt][1];
            Os[r1l * 264 + c] = O[dt][2]; Os[r1l * 264 + c + 1] = O[dt][3];
        }
        if (t4 == 0) {
            ml[r0l] = m0; ml[64 + r0l] = l0;
            ml[r1l] = m1; ml[64 + r1l] = l1;
        }
    }
    __syncthreads();
    if (grp == 0) {
        float mo0 = ml[r0l], lo0 = ml[64 + r0l];
        float mo1 = ml[r1l], lo1 = ml[64 + r1l];
        float mm0 = fmaxf(m0, mo0), mm1 = fmaxf(m1, mo1);
        float wa0 = __expf(m0 - mm0), wb0 = __expf(mo0 - mm0);
        float wa1 = __expf(m1 - mm1), wb1 = __expf(mo1 - mm1);
        float inv0 = 1.f / (l0 * wa0 + lo0 * wb0);
        float inv1 = 1.f / (l1 * wa1 + lo1 * wb1);
        float2* o0 = reinterpret_cast<float2*>(Out + (size_t)rg0 * DD);
        float2* o1 = reinterpret_cast<float2*>(Out + (size_t)rg1 * DD);
        #pragma unroll
        for (int dt = 0; dt < 32; ++dt) {
            int c = 8 * dt + 2 * t4;
            o0[4 * dt + t4] = make_float2(
                (O[dt][0] * wa0 + Os[r0l * 264 + c] * wb0) * inv0,
                (O[dt][1] * wa0 + Os[r0l * 264 + c + 1] * wb0) * inv0);
            o1[4 * dt + t4] = make_float2(
                (O[dt][2] * wa1 + Os[r1l * 264 + c] * wb1) * inv1,
                (O[dt][3] * wa1 + Os[r1l * 264 + c + 1] * wb1) * inv1);
        }
    }
}

// ---------------------------------------------------------------------------
extern "C" void kernel_launch(void* const* d_in, const int* in_sizes, int n_in,
                              void* d_out, int out_size) {
    const float* X  = (const float*)d_in[0];
    const int*   A  = (const int*)d_in[1];
    const float* Wq = (const float*)d_in[2];
    const float* Wk = (const float*)d_in[3];
    const float* Wv = (const float*)d_in[4];
    float* Out = (float*)d_out;

    static int attr_set = 0;
    const int smem_bytes = 196608;
    if (!attr_set) {
        cudaFuncSetAttribute(attn_kernel, cudaFuncAttributeMaxDynamicSharedMemorySize,
                             smem_bytes);
        attr_set = 1;
    }

    pack_mask_kernel<<<NN, 256>>>(A);
    qkv_kernel<<<dim3(NN / 64, DD / 64, 3), 256>>>(X, Wq, Wk, Wv);
    attn_kernel<<<NN / BM, 256, smem_bytes>>>(Out);
}

// round 8
// speedup vs baseline: 7.6498x; 1.2218x over previous
#include <cuda_runtime.h>
#include <cuda_fp16.h>
#include <cstdint>

#define NN 8192
#define DD 256
#define BM 64
#define BN 32

// ---------------- device global scratch ----------------
__device__ __half g_Qhi[NN * DD], g_Qlo[NN * DD];
__device__ __half g_Khi[NN * DD], g_Klo[NN * DD];
__device__ __half g_V[NN * DD];                       // single fp16
__device__ __half g_Xhi[NN * DD], g_Xlo[NN * DD];
__device__ __half g_Whi[3 * DD * DD], g_Wlo[3 * DD * DD];  // [z][col][k] (transposed)
__device__ uint32_t g_mask[NN * (NN / 32)];

// ---------------- helpers ----------------
__device__ __forceinline__ uint32_t smem_u32(const void* p) {
    uint32_t a;
    asm("{ .reg .u64 t; cvta.to.shared.u64 t, %1; cvt.u32.u64 %0, t; }" : "=r"(a) : "l"(p));
    return a;
}
// 16B-chunk XOR swizzle within 128B window; rows are 512B (256 fp16)
__device__ __forceinline__ uint32_t swz(int r, int c) {
    return (uint32_t)(r * 512 + ((((c ^ r) & 7) | (c & 24)) << 4));
}
__device__ __forceinline__ void ldm_x4(uint32_t a, uint32_t* r) {
    asm volatile("ldmatrix.sync.aligned.m8n8.x4.shared.b16 {%0,%1,%2,%3}, [%4];"
                 : "=r"(r[0]), "=r"(r[1]), "=r"(r[2]), "=r"(r[3]) : "r"(a));
}
__device__ __forceinline__ void ldm_x4t(uint32_t a, uint32_t* r) {
    asm volatile("ldmatrix.sync.aligned.m8n8.x4.trans.shared.b16 {%0,%1,%2,%3}, [%4];"
                 : "=r"(r[0]), "=r"(r[1]), "=r"(r[2]), "=r"(r[3]) : "r"(a));
}
__device__ __forceinline__ void mma_f16(float* c, const uint32_t* a, const uint32_t* b) {
    asm volatile(
        "mma.sync.aligned.m16n8k16.row.col.f32.f16.f16.f32 "
        "{%0,%1,%2,%3},{%4,%5,%6,%7},{%8,%9},{%0,%1,%2,%3};"
        : "+f"(c[0]), "+f"(c[1]), "+f"(c[2]), "+f"(c[3])
        : "r"(a[0]), "r"(a[1]), "r"(a[2]), "r"(a[3]), "r"(b[0]), "r"(b[1]));
}
__device__ __forceinline__ void cpa16(uint32_t dst, const void* src) {
    asm volatile("cp.async.cg.shared.global [%0], [%1], 16;" :: "r"(dst), "l"(src));
}
#define CPA_COMMIT() asm volatile("cp.async.commit_group;")
#define CPA_WAIT0() asm volatile("cp.async.wait_group 0;")
#define CPA_WAIT1() asm volatile("cp.async.wait_group 1;")
#define GBAR(id) asm volatile("bar.sync %0, 128;" :: "r"(id) : "memory")

// tile loader: R rows x 256 fp16 (512B rows), NT participating threads
template <int R, int NT>
__device__ __forceinline__ void cpa_tile(uint32_t sbase, const __half* g,
                                         int row0, int ltid) {
    const char* gp = (const char*)(g + (size_t)row0 * DD);
    #pragma unroll
    for (int t = 0; t < (R * 32) / NT; ++t) {
        int idx = ltid + t * NT;
        int r = idx >> 5, c = idx & 31;
        cpa16(sbase + swz(r, c), gp + r * 512 + c * 16);
    }
}

// ---------------------------------------------------------------------------
// Pack adjacency to bitmask (int4 loads). grid=NN, block=256.
// ---------------------------------------------------------------------------
__global__ __launch_bounds__(256)
void pack_mask_kernel(const int* __restrict__ A) {
    const int row = blockIdx.x;
    const int lane = threadIdx.x & 31, w = threadIdx.x >> 5;
    const int4* arow = (const int4*)(A + (size_t)row * NN);
    #pragma unroll
    for (int it = 0; it < 8; ++it) {
        int blk = w + it * 8;
        int col0 = blk * 128 + lane * 4;
        int4 v = arow[blk * 32 + lane];
        uint32_t nib = (v.x != 0 ? 1u : 0u) | (v.y != 0 ? 2u : 0u) |
                       (v.z != 0 ? 4u : 0u) | (v.w != 0 ? 8u : 0u);
        uint32_t d = (uint32_t)(row - col0);
        if (d < 4u) nib |= 1u << d;
        uint32_t bits = nib << (4 * (lane & 7));
        bits |= __shfl_xor_sync(0xffffffffu, bits, 1);
        bits |= __shfl_xor_sync(0xffffffffu, bits, 2);
        bits |= __shfl_xor_sync(0xffffffffu, bits, 4);
        if ((lane & 7) == 0)
            g_mask[(size_t)row * (NN / 32) + blk * 4 + (lane >> 3)] = bits;
    }
}

// ---------------------------------------------------------------------------
// Split X -> fp16 hi/lo; W -> fp16 hi/lo TRANSPOSED to [col][k].
// grid 2048 + 768 blocks of 256.
// ---------------------------------------------------------------------------
__global__ __launch_bounds__(256)
void split_kernel(const float* __restrict__ X, const float* __restrict__ Wq,
                  const float* __restrict__ Wk, const float* __restrict__ Wv) {
    const int b = blockIdx.x, tid = threadIdx.x;
    if (b < 2048) {
        int i = b * 256 + tid;   // float4 index over X
        float4 v = reinterpret_cast<const float4*>(X)[i];
        __half2 h0 = __floats2half2_rn(v.x, v.y);
        __half2 h1 = __floats2half2_rn(v.z, v.w);
        float2 f0 = __half22float2(h0), f1 = __half22float2(h1);
        __half2 l0 = __floats2half2_rn(v.x - f0.x, v.y - f0.y);
        __half2 l1 = __floats2half2_rn(v.z - f1.x, v.w - f1.y);
        reinterpret_cast<__half2*>(g_Xhi)[2 * i] = h0;
        reinterpret_cast<__half2*>(g_Xhi)[2 * i + 1] = h1;
        reinterpret_cast<__half2*>(g_Xlo)[2 * i] = l0;
        reinterpret_cast<__half2*>(g_Xlo)[2 * i + 1] = l1;
    } else {
        int j = (b - 2048) * 256 + tid;          // elem over 3*65536
        int z = j >> 16, e = j & 65535;
        int k = e >> 8, col = e & 255;
        const float* W = (z == 0) ? Wq : (z == 1) ? Wk : Wv;
        float v = W[k * DD + col];
        __half h = __float2half_rn(v);
        g_Whi[z * DD * DD + col * DD + k] = h;
        g_Wlo[z * DD * DD + col * DD + k] = __float2half_rn(v - __half2float(h));
    }
}

// ---------------------------------------------------------------------------
// QKV projection on tensor cores (fp16 x3 products).
// grid (NN/64, 2, 3), block 256 (8 warps: 4 row-split x 2 col-split of 64).
// smem: Xhi 32K | Xlo 32K | Whi 64K | Wlo 64K = 192K
// ---------------------------------------------------------------------------
__global__ __launch_bounds__(256, 1)
void qkv_mma_kernel() {
    extern __shared__ char smem[];
    const int tid = threadIdx.x, warp = tid >> 5, lane = tid & 31;
    const int roww = warp & 3, colw = warp >> 2;
    const int g = lane >> 2, t4 = lane & 3;
    const int rowbase = blockIdx.x * 64, colbase = blockIdx.y * 128;
    const int z = blockIdx.z;

    const uint32_t sbase = smem_u32(smem);
    const uint32_t XH = sbase, XL = sbase + 32768;
    const uint32_t WH = sbase + 65536, WL = sbase + 131072;

    cpa_tile<64, 256>(XH, g_Xhi, rowbase, tid);
    cpa_tile<64, 256>(XL, g_Xlo, rowbase, tid);
    cpa_tile<128, 256>(WH, g_Whi + (size_t)z * DD * DD + (size_t)colbase * DD, 0, tid);
    cpa_tile<128, 256>(WL, g_Wlo + (size_t)z * DD * DD + (size_t)colbase * DD, 0, tid);
    CPA_COMMIT();
    CPA_WAIT0();
    __syncthreads();

    float C[8][4];
    #pragma unroll
    for (int nt = 0; nt < 8; ++nt) {
        C[nt][0] = 0.f; C[nt][1] = 0.f; C[nt][2] = 0.f; C[nt][3] = 0.f;
    }

    const int qr = 16 * roww + (lane & 15);
    const int qcsel = lane >> 4;
    const int bj_half = lane >> 4;
    const int bkcsel = (lane >> 3) & 1;
    const int br8 = lane & 7;

    #pragma unroll 4
    for (int kk = 0; kk < 16; ++kk) {
        uint32_t aH[4], aL[4];
        ldm_x4(XH + swz(qr, 2 * kk + qcsel), aH);
        ldm_x4(XL + swz(qr, 2 * kk + qcsel), aL);
        #pragma unroll
        for (int jjp = 0; jjp < 4; ++jjp) {
            int colrow = 64 * colw + 8 * (2 * jjp + bj_half) + br8;
            int kc = 2 * kk + bkcsel;
            uint32_t bH[4], bL[4];
            ldm_x4(WH + swz(colrow, kc), bH);
            ldm_x4(WL + swz(colrow, kc), bL);
            mma_f16(C[2 * jjp], aH, bH);
            mma_f16(C[2 * jjp], aL, bH);
            mma_f16(C[2 * jjp], aH, bL);
            mma_f16(C[2 * jjp + 1], aH, bH + 2);
            mma_f16(C[2 * jjp + 1], aL, bH + 2);
            mma_f16(C[2 * jjp + 1], aH, bL + 2);
        }
    }

    // epilogue
    const int r0 = rowbase + 16 * roww + g, r1 = r0 + 8;
    #pragma unroll
    for (int nt = 0; nt < 8; ++nt) {
        int col = colbase + 64 * colw + 8 * nt + 2 * t4;
        if (z == 2) {
            *reinterpret_cast<__half2*>(&g_V[(size_t)r0 * DD + col]) =
                __floats2half2_rn(C[nt][0], C[nt][1]);
            *reinterpret_cast<__half2*>(&g_V[(size_t)r1 * DD + col]) =
                __floats2half2_rn(C[nt][2], C[nt][3]);
        } else {
            __half* Oh = (z == 0) ? g_Qhi : g_Khi;
            __half* Ol = (z == 0) ? g_Qlo : g_Klo;
            __half2 h0 = __floats2half2_rn(C[nt][0], C[nt][1]);
            float2 f0 = __half22float2(h0);
            __half2 l0 = __floats2half2_rn(C[nt][0] - f0.x, C[nt][1] - f0.y);
            __half2 h1 = __floats2half2_rn(C[nt][2], C[nt][3]);
            float2 f1 = __half22float2(h1);
            __half2 l1 = __floats2half2_rn(C[nt][2] - f1.x, C[nt][3] - f1.y);
            *reinterpret_cast<__half2*>(&Oh[(size_t)r0 * DD + col]) = h0;
            *reinterpret_cast<__half2*>(&Ol[(size_t)r0 * DD + col]) = l0;
            *reinterpret_cast<__half2*>(&Oh[(size_t)r1 * DD + col]) = h1;
            *reinterpret_cast<__half2*>(&Ol[(size_t)r1 * DD + col]) = l1;
        }
    }
}

// ---------------------------------------------------------------------------
// Flash attention, fp16 mma.sync, 8 warps in 2 ping-pong groups.
// S: 3 products (QhKh + QlKh + QhKl). PV: 2 products ((Ph+Pl)·V), V single fp16.
// smem: Q hi/lo 64K | group0 {Khi,Klo,V} 48K | group1 48K = 160K
// ---------------------------------------------------------------------------
__global__ __launch_bounds__(256, 1)
void attn_kernel(float* __restrict__ Out) {
    extern __shared__ char smem[];
    const int tid = threadIdx.x, warp = tid >> 5, lane = tid & 31;
    const int grp = warp >> 2, wg = warp & 3, ltid = tid & 127;
    const int g = lane >> 2, t4 = lane & 3;
    const int rowbase = blockIdx.x * BM;

    const uint32_t sbase = smem_u32(smem);
    const uint32_t sQH = sbase, sQL = sbase + 32768;
    const uint32_t KB = sbase + 65536 + grp * 49152;
    const uint32_t KH = KB, KL = KB + 16384, VS = KB + 32768;
    const int barid = grp + 1;

    cpa_tile<BM, 256>(sQH, g_Qhi, rowbase, tid);
    cpa_tile<BM, 256>(sQL, g_Qlo, rowbase, tid);
    cpa_tile<BN, 128>(KH, g_Khi, grp * BN, ltid);
    cpa_tile<BN, 128>(KL, g_Klo, grp * BN, ltid);
    CPA_COMMIT();

    float O[32][4];
    #pragma unroll
    for (int dt = 0; dt < 32; ++dt) {
        O[dt][0] = 0.f; O[dt][1] = 0.f; O[dt][2] = 0.f; O[dt][3] = 0.f;
    }
    float m0 = -1e30f, m1 = -1e30f, l0 = 0.f, l1 = 0.f;

    const int rg0 = rowbase + 16 * wg + g;
    const int rg1 = rg0 + 8;
    const uint32_t* mrow0 = g_mask + (size_t)rg0 * (NN / 32);
    const uint32_t* mrow1 = g_mask + (size_t)rg1 * (NN / 32);

    const int qr = 16 * wg + (lane & 15);
    const int qcsel = lane >> 4;
    const int k_j_half = lane >> 4;
    const int k_kcsel = (lane >> 3) & 1;
    const int kr8 = lane & 7;
    const int v_dtsel = lane >> 4;
    const int vlane = lane & 15;

    const int NBLK = NN / BN;
    for (int i = 0; i < NBLK / 2; ++i) {
        const int b = 2 * i + grp;

        cpa_tile<BN, 128>(VS, g_V, b * BN, ltid);
        CPA_COMMIT();
        CPA_WAIT1();               // K[b] (and Q) landed
        GBAR(barid);

        // ---- S = Q K^T (16x32 per warp), fp16 x3 ----
        float S[4][4] = {};
        #pragma unroll 4
        for (int kk = 0; kk < 16; ++kk) {
            uint32_t aH[4], aL[4];
            ldm_x4(sQH + swz(qr, 2 * kk + qcsel), aH);
            ldm_x4(sQL + swz(qr, 2 * kk + qcsel), aL);
            #pragma unroll
            for (int jjp = 0; jjp < 2; ++jjp) {
                int krow = 8 * (2 * jjp + k_j_half) + kr8;
                int kc = 2 * kk + k_kcsel;
                uint32_t bH[4], bL[4];
                ldm_x4(KH + swz(krow, kc), bH);
                ldm_x4(KL + swz(krow, kc), bL);
                mma_f16(S[2 * jjp], aH, bH);
                mma_f16(S[2 * jjp], aL, bH);
                mma_f16(S[2 * jjp], aH, bL);
                mma_f16(S[2 * jjp + 1], aH, bH + 2);
                mma_f16(S[2 * jjp + 1], aL, bH + 2);
                mma_f16(S[2 * jjp + 1], aH, bL + 2);
            }
        }
        GBAR(barid);               // group done reading K[b]

        if (i + 1 < NBLK / 2) {
            cpa_tile<BN, 128>(KH, g_Khi, (b + 2) * BN, ltid);
            cpa_tile<BN, 128>(KL, g_Klo, (b + 2) * BN, ltid);
            CPA_COMMIT();
            CPA_WAIT1();           // V[b] landed (K still in flight)
        } else {
            CPA_WAIT0();
        }

        // ---- mask + online softmax ----
        const uint32_t mw0 = mrow0[b], mw1 = mrow1[b];
        float pv[4][4];
        float mt0 = -1e30f, mt1 = -1e30f;
        #pragma unroll
        for (int j = 0; j < 4; ++j)
            #pragma unroll
            for (int e = 0; e < 2; ++e) {
                int bit = 8 * j + 2 * t4 + e;
                float s0 = ((mw0 >> bit) & 1u) ? S[j][e] : -1e30f;
                float s1 = ((mw1 >> bit) & 1u) ? S[j][2 + e] : -1e30f;
                pv[j][e] = s0; pv[j][2 + e] = s1;
                mt0 = fmaxf(mt0, s0); mt1 = fmaxf(mt1, s1);
            }
        mt0 = fmaxf(mt0, __shfl_xor_sync(0xffffffffu, mt0, 1));
        mt0 = fmaxf(mt0, __shfl_xor_sync(0xffffffffu, mt0, 2));
        mt1 = fmaxf(mt1, __shfl_xor_sync(0xffffffffu, mt1, 1));
        mt1 = fmaxf(mt1, __shfl_xor_sync(0xffffffffu, mt1, 2));

        const float mn0 = fmaxf(m0, mt0), mn1 = fmaxf(m1, mt1);
        const float sc0 = __expf(m0 - mn0), sc1 = __expf(m1 - mn1);
        float rs0 = 0.f, rs1 = 0.f;
        #pragma unroll
        for (int j = 0; j < 4; ++j)
            #pragma unroll
            for (int e = 0; e < 2; ++e) {
                int bit = 8 * j + 2 * t4 + e;
                float p0 = ((mw0 >> bit) & 1u) ? __expf(pv[j][e] - mn0) : 0.f;
                float p1 = ((mw1 >> bit) & 1u) ? __expf(pv[j][2 + e] - mn1) : 0.f;
                pv[j][e] = p0; pv[j][2 + e] = p1;
                rs0 += p0; rs1 += p1;
            }
        rs0 += __shfl_xor_sync(0xffffffffu, rs0, 1);
        rs0 += __shfl_xor_sync(0xffffffffu, rs0, 2);
        rs1 += __shfl_xor_sync(0xffffffffu, rs1, 1);
        rs1 += __shfl_xor_sync(0xffffffffu, rs1, 2);
        l0 = l0 * sc0 + rs0;
        l1 = l1 * sc1 + rs1;
        m0 = mn0; m1 = mn1;

        if (__ballot_sync(0xffffffffu, (sc0 != 1.f) || (sc1 != 1.f))) {
            #pragma unroll
            for (int dt = 0; dt < 32; ++dt) {
                O[dt][0] *= sc0; O[dt][1] *= sc0;
                O[dt][2] *= sc1; O[dt][3] *= sc1;
            }
        }

        // ---- P -> fp16 hi/lo A-fragments ----
        uint32_t Ph[4][2], Pl[4][2];
        #pragma unroll
        for (int j = 0; j < 4; ++j) {
            __half2 hh = __floats2half2_rn(pv[j][0], pv[j][1]);
            float2 fh = __half22float2(hh);
            __half2 ll = __floats2half2_rn(pv[j][0] - fh.x, pv[j][1] - fh.y);
            Ph[j][0] = *reinterpret_cast<uint32_t*>(&hh);
            Pl[j][0] = *reinterpret_cast<uint32_t*>(&ll);
            __half2 hh2 = __floats2half2_rn(pv[j][2], pv[j][3]);
            float2 fh2 = __half22float2(hh2);
            __half2 ll2 = __floats2half2_rn(pv[j][2] - fh2.x, pv[j][3] - fh2.y);
            Ph[j][1] = *reinterpret_cast<uint32_t*>(&hh2);
            Pl[j][1] = *reinterpret_cast<uint32_t*>(&ll2);
        }

        GBAR(barid);               // V[b] visible to whole group

        // ---- O += (Ph+Pl) V (V single fp16, x4 trans) ----
        #pragma unroll
        for (int kp = 0; kp < 2; ++kp) {
            uint32_t aH[4] = {Ph[2 * kp][0], Ph[2 * kp][1], Ph[2 * kp + 1][0], Ph[2 * kp + 1][1]};
            uint32_t aL[4] = {Pl[2 * kp][0], Pl[2 * kp][1], Pl[2 * kp + 1][0], Pl[2 * kp + 1][1]};
            const int vr = 16 * kp + vlane;
            #pragma unroll
            for (int dtp = 0; dtp < 16; ++dtp) {
                int vc = 2 * dtp + v_dtsel;
                uint32_t bV[4];
                ldm_x4t(VS + swz(vr, vc), bV);
                mma_f16(O[2 * dtp], aH, bV);
                mma_f16(O[2 * dtp], aL, bV);
                mma_f16(O[2 * dtp + 1], aH, bV + 2);
                mma_f16(O[2 * dtp + 1], aL, bV + 2);
            }
        }
        GBAR(barid);               // group done reading V[b]
    }

    // ---- merge groups ----
    __syncthreads();
    float* Os = reinterpret_cast<float*>(smem + 65536);   // [64][264] padded
    float* ml = reinterpret_cast<float*>(smem + 133120);  // m[64], l[64]
    const int r0l = 16 * wg + g, r1l = r0l + 8;
    if (grp == 1) {
        #pragma unroll
        for (int dt = 0; dt < 32; ++dt) {
            int c = 8 * dt + 2 * t4;
            Os[r0l * 264 + c] = O[dt][0]; Os[r0l * 264 + c + 1] = O[dt][1];
            Os[r1l * 264 + c] = O[dt][2]; Os[r1l * 264 + c + 1] = O[dt][3];
        }
        if (t4 == 0) {
            ml[r0l] = m0; ml[64 + r0l] = l0;
            ml[r1l] = m1; ml[64 + r1l] = l1;
        }
    }
    __syncthreads();
    if (grp == 0) {
        float mo0 = ml[r0l], lo0 = ml[64 + r0l];
        float mo1 = ml[r1l], lo1 = ml[64 + r1l];
        float mm0 = fmaxf(m0, mo0), mm1 = fmaxf(m1, mo1);
        float wa0 = __expf(m0 - mm0), wb0 = __expf(mo0 - mm0);
        float wa1 = __expf(m1 - mm1), wb1 = __expf(mo1 - mm1);
        float inv0 = 1.f / (l0 * wa0 + lo0 * wb0);
        float inv1 = 1.f / (l1 * wa1 + lo1 * wb1);
        float2* o0 = reinterpret_cast<float2*>(Out + (size_t)rg0 * DD);
        float2* o1 = reinterpret_cast<float2*>(Out + (size_t)rg1 * DD);
        #pragma unroll
        for (int dt = 0; dt < 32; ++dt) {
            int c = 8 * dt + 2 * t4;
            o0[4 * dt + t4] = make_float2(
                (O[dt][0] * wa0 + Os[r0l * 264 + c] * wb0) * inv0,
                (O[dt][1] * wa0 + Os[r0l * 264 + c + 1] * wb0) * inv0);
            o1[4 * dt + t4] = make_float2(
                (O[dt][2] * wa1 + Os[r1l * 264 + c] * wb1) * inv1,
                (O[dt][3] * wa1 + Os[r1l * 264 + c + 1] * wb1) * inv1);
        }
    }
}

// ---------------------------------------------------------------------------
extern "C" void kernel_launch(void* const* d_in, const int* in_sizes, int n_in,
                              void* d_out, int out_size) {
    const float* X  = (const float*)d_in[0];
    const int*   A  = (const int*)d_in[1];
    const float* Wq = (const float*)d_in[2];
    const float* Wk = (const float*)d_in[3];
    const float* Wv = (const float*)d_in[4];
    float* Out = (float*)d_out;

    static int attr_set = 0;
    const int smem_attn = 163840;
    const int smem_qkv = 196608;
    if (!attr_set) {
        cudaFuncSetAttribute(attn_kernel, cudaFuncAttributeMaxDynamicSharedMemorySize,
                             smem_attn);
        cudaFuncSetAttribute(qkv_mma_kernel, cudaFuncAttributeMaxDynamicSharedMemorySize,
                             smem_qkv);
        attr_set = 1;
    }

    pack_mask_kernel<<<NN, 256>>>(A);
    split_kernel<<<2048 + 768, 256>>>(X, Wq, Wk, Wv);
    qkv_mma_kernel<<<dim3(NN / 64, 2, 3), 256, smem_qkv>>>();
    attn_kernel<<<NN / BM, 256, smem_attn>>>(Out);
}

// round 11
// speedup vs baseline: 8.9569x; 1.1709x over previous
#include <cuda_runtime.h>
#include <cuda_fp16.h>
#include <cstdint>

#define NN 8192
#define DD 256
#define BM 64
#define BN 32

// ---------------- device global scratch ----------------
__device__ __half g_Qhi[NN * DD], g_Qlo[NN * DD];
__device__ __half g_Khi[NN * DD], g_Klo[NN * DD];
__device__ __half g_V[NN * DD];                       // single fp16
__device__ __half g_Xhi[NN * DD], g_Xlo[NN * DD];
__device__ __half g_Whi[3 * DD * DD], g_Wlo[3 * DD * DD];  // [z][col][k] (transposed)
__device__ uint32_t g_mask[NN * (NN / 32)];

// ---------------- helpers ----------------
__device__ __forceinline__ uint32_t smem_u32(const void* p) {
    uint32_t a;
    asm("{ .reg .u64 t; cvta.to.shared.u64 t, %1; cvt.u32.u64 %0, t; }" : "=r"(a) : "l"(p));
    return a;
}
// 16B-chunk XOR swizzle within 128B window; rows are 512B (256 fp16)
__device__ __forceinline__ uint32_t swz(int r, int c) {
    return (uint32_t)(r * 512 + ((((c ^ r) & 7) | (c & 24)) << 4));
}
__device__ __forceinline__ void ldm_x4(uint32_t a, uint32_t* r) {
    asm volatile("ldmatrix.sync.aligned.m8n8.x4.shared.b16 {%0,%1,%2,%3}, [%4];"
                 : "=r"(r[0]), "=r"(r[1]), "=r"(r[2]), "=r"(r[3]) : "r"(a));
}
__device__ __forceinline__ void ldm_x4t(uint32_t a, uint32_t* r) {
    asm volatile("ldmatrix.sync.aligned.m8n8.x4.trans.shared.b16 {%0,%1,%2,%3}, [%4];"
                 : "=r"(r[0]), "=r"(r[1]), "=r"(r[2]), "=r"(r[3]) : "r"(a));
}
__device__ __forceinline__ void mma_f16(float* c, const uint32_t* a, const uint32_t* b) {
    asm volatile(
        "mma.sync.aligned.m16n8k16.row.col.f32.f16.f16.f32 "
        "{%0,%1,%2,%3},{%4,%5,%6,%7},{%8,%9},{%0,%1,%2,%3};"
        : "+f"(c[0]), "+f"(c[1]), "+f"(c[2]), "+f"(c[3])
        : "r"(a[0]), "r"(a[1]), "r"(a[2]), "r"(a[3]), "r"(b[0]), "r"(b[1]));
}
__device__ __forceinline__ void cpa16(uint32_t dst, const void* src) {
    asm volatile("cp.async.cg.shared.global [%0], [%1], 16;" :: "r"(dst), "l"(src));
}
#define CPA_COMMIT() asm volatile("cp.async.commit_group;")
#define CPA_WAIT0() asm volatile("cp.async.wait_group 0;")
#define CPA_WAIT1() asm volatile("cp.async.wait_group 1;")
#define GBAR(id) asm volatile("bar.sync %0, 128;" :: "r"(id) : "memory")

// tile loader: R rows x 256 fp16 (512B rows), NT participating threads
template <int R, int NT>
__device__ __forceinline__ void cpa_tile(uint32_t sbase, const __half* g,
                                         int row0, int ltid) {
    const char* gp = (const char*)(g + (size_t)row0 * DD);
    #pragma unroll
    for (int t = 0; t < (R * 32) / NT; ++t) {
        int idx = ltid + t * NT;
        int r = idx >> 5, c = idx & 31;
        cpa16(sbase + swz(r, c), gp + r * 512 + c * 16);
    }
}

// ---------------------------------------------------------------------------
// Pack adjacency to bitmask (int4 loads). grid=NN, block=256.
// ---------------------------------------------------------------------------
__global__ __launch_bounds__(256)
void pack_mask_kernel(const int* __restrict__ A) {
    const int row = blockIdx.x;
    const int lane = threadIdx.x & 31, w = threadIdx.x >> 5;
    const int4* arow = (const int4*)(A + (size_t)row * NN);
    #pragma unroll
    for (int it = 0; it < 8; ++it) {
        int blk = w + it * 8;
        int col0 = blk * 128 + lane * 4;
        int4 v = arow[blk * 32 + lane];
        uint32_t nib = (v.x != 0 ? 1u : 0u) | (v.y != 0 ? 2u : 0u) |
                       (v.z != 0 ? 4u : 0u) | (v.w != 0 ? 8u : 0u);
        uint32_t d = (uint32_t)(row - col0);
        if (d < 4u) nib |= 1u << d;
        uint32_t bits = nib << (4 * (lane & 7));
        bits |= __shfl_xor_sync(0xffffffffu, bits, 1);
        bits |= __shfl_xor_sync(0xffffffffu, bits, 2);
        bits |= __shfl_xor_sync(0xffffffffu, bits, 4);
        if ((lane & 7) == 0)
            g_mask[(size_t)row * (NN / 32) + blk * 4 + (lane >> 3)] = bits;
    }
}

// ---------------------------------------------------------------------------
// Split X -> fp16 hi/lo; W -> fp16 hi/lo TRANSPOSED to [col][k].
// grid 2048 + 768 blocks of 256.
// ---------------------------------------------------------------------------
__global__ __launch_bounds__(256)
void split_kernel(const float* __restrict__ X, const float* __restrict__ Wq,
                  const float* __restrict__ Wk, const float* __restrict__ Wv) {
    const int b = blockIdx.x, tid = threadIdx.x;
    if (b < 2048) {
        int i = b * 256 + tid;   // float4 index over X
        float4 v = reinterpret_cast<const float4*>(X)[i];
        __half2 h0 = __floats2half2_rn(v.x, v.y);
        __half2 h1 = __floats2half2_rn(v.z, v.w);
        float2 f0 = __half22float2(h0), f1 = __half22float2(h1);
        __half2 l0 = __floats2half2_rn(v.x - f0.x, v.y - f0.y);
        __half2 l1 = __floats2half2_rn(v.z - f1.x, v.w - f1.y);
        reinterpret_cast<__half2*>(g_Xhi)[2 * i] = h0;
        reinterpret_cast<__half2*>(g_Xhi)[2 * i + 1] = h1;
        reinterpret_cast<__half2*>(g_Xlo)[2 * i] = l0;
        reinterpret_cast<__half2*>(g_Xlo)[2 * i + 1] = l1;
    } else {
        int j = (b - 2048) * 256 + tid;          // elem over 3*65536
        int z = j >> 16, e = j & 65535;
        int k = e >> 8, col = e & 255;
        const float* W = (z == 0) ? Wq : (z == 1) ? Wk : Wv;
        float v = W[k * DD + col];
        __half h = __float2half_rn(v);
        g_Whi[z * DD * DD + col * DD + k] = h;
        g_Wlo[z * DD * DD + col * DD + k] = __float2half_rn(v - __half2float(h));
    }
}

// ---------------------------------------------------------------------------
// QKV projection on tensor cores (fp16 x3 products).
// grid (NN/64, 2, 3), block 256 (8 warps: 4 row-split x 2 col-split of 64).
// smem: Xhi 32K | Xlo 32K | Whi 64K | Wlo 64K = 192K
// ---------------------------------------------------------------------------
__global__ __launch_bounds__(256, 1)
void qkv_mma_kernel() {
    extern __shared__ char smem[];
    const int tid = threadIdx.x, warp = tid >> 5, lane = tid & 31;
    const int roww = warp & 3, colw = warp >> 2;
    const int g = lane >> 2, t4 = lane & 3;
    const int rowbase = blockIdx.x * 64, colbase = blockIdx.y * 128;
    const int z = blockIdx.z;

    const uint32_t sbase = smem_u32(smem);
    const uint32_t XH = sbase, XL = sbase + 32768;
    const uint32_t WH = sbase + 65536, WL = sbase + 131072;

    cpa_tile<64, 256>(XH, g_Xhi, rowbase, tid);
    cpa_tile<64, 256>(XL, g_Xlo, rowbase, tid);
    cpa_tile<128, 256>(WH, g_Whi + (size_t)z * DD * DD + (size_t)colbase * DD, 0, tid);
    cpa_tile<128, 256>(WL, g_Wlo + (size_t)z * DD * DD + (size_t)colbase * DD, 0, tid);
    CPA_COMMIT();
    CPA_WAIT0();
    __syncthreads();

    float C[8][4];
    #pragma unroll
    for (int nt = 0; nt < 8; ++nt) {
        C[nt][0] = 0.f; C[nt][1] = 0.f; C[nt][2] = 0.f; C[nt][3] = 0.f;
    }

    const int qr = 16 * roww + (lane & 15);
    const int qcsel = lane >> 4;
    const int bj_half = lane >> 4;
    const int bkcsel = (lane >> 3) & 1;
    const int br8 = lane & 7;

    #pragma unroll 4
    for (int kk = 0; kk < 16; ++kk) {
        uint32_t aH[4], aL[4];
        ldm_x4(XH + swz(qr, 2 * kk + qcsel), aH);
        ldm_x4(XL + swz(qr, 2 * kk + qcsel), aL);
        #pragma unroll
        for (int jjp = 0; jjp < 4; ++jjp) {
            int colrow = 64 * colw + 8 * (2 * jjp + bj_half) + br8;
            int kc = 2 * kk + bkcsel;
            uint32_t bH[4], bL[4];
            ldm_x4(WH + swz(colrow, kc), bH);
            ldm_x4(WL + swz(colrow, kc), bL);
            mma_f16(C[2 * jjp], aH, bH);
            mma_f16(C[2 * jjp], aL, bH);
            mma_f16(C[2 * jjp], aH, bL);
            mma_f16(C[2 * jjp + 1], aH, bH + 2);
            mma_f16(C[2 * jjp + 1], aL, bH + 2);
            mma_f16(C[2 * jjp + 1], aH, bL + 2);
        }
    }

    // epilogue
    const int r0 = rowbase + 16 * roww + g, r1 = r0 + 8;
    #pragma unroll
    for (int nt = 0; nt < 8; ++nt) {
        int col = colbase + 64 * colw + 8 * nt + 2 * t4;
        if (z == 2) {
            *reinterpret_cast<__half2*>(&g_V[(size_t)r0 * DD + col]) =
                __floats2half2_rn(C[nt][0], C[nt][1]);
            *reinterpret_cast<__half2*>(&g_V[(size_t)r1 * DD + col]) =
                __floats2half2_rn(C[nt][2], C[nt][3]);
        } else {
            __half* Oh = (z == 0) ? g_Qhi : g_Khi;
            __half* Ol = (z == 0) ? g_Qlo : g_Klo;
            __half2 h0 = __floats2half2_rn(C[nt][0], C[nt][1]);
            float2 f0 = __half22float2(h0);
            __half2 l0 = __floats2half2_rn(C[nt][0] - f0.x, C[nt][1] - f0.y);
            __half2 h1 = __floats2half2_rn(C[nt][2], C[nt][3]);
            float2 f1 = __half22float2(h1);
            __half2 l1 = __floats2half2_rn(C[nt][2] - f1.x, C[nt][3] - f1.y);
            *reinterpret_cast<__half2*>(&Oh[(size_t)r0 * DD + col]) = h0;
            *reinterpret_cast<__half2*>(&Ol[(size_t)r0 * DD + col]) = l0;
            *reinterpret_cast<__half2*>(&Oh[(size_t)r1 * DD + col]) = h1;
            *reinterpret_cast<__half2*>(&Ol[(size_t)r1 * DD + col]) = l1;
        }
    }
}

// ---------------------------------------------------------------------------
// Flash attention, fp16 mma.sync, 8 warps in 2 ping-pong groups.
// S: 3 products (QhKh + QlKh + QhKl). PV: 1 product (fp16 P, fp16 V),
// with l summed from the ROUNDED p so numerator/denominator errors cancel.
// smem: Q hi/lo 64K | group0 {Khi,Klo,V} 48K | group1 48K = 160K
// ---------------------------------------------------------------------------
__global__ __launch_bounds__(256, 1)
void attn_kernel(float* __restrict__ Out) {
    extern __shared__ char smem[];
    const int tid = threadIdx.x, warp = tid >> 5, lane = tid & 31;
    const int grp = warp >> 2, wg = warp & 3, ltid = tid & 127;
    const int g = lane >> 2, t4 = lane & 3;
    const int rowbase = blockIdx.x * BM;

    const uint32_t sbase = smem_u32(smem);
    const uint32_t sQH = sbase, sQL = sbase + 32768;
    const uint32_t KB = sbase + 65536 + grp * 49152;
    const uint32_t KH = KB, KL = KB + 16384, VS = KB + 32768;
    const int barid = grp + 1;

    cpa_tile<BM, 256>(sQH, g_Qhi, rowbase, tid);
    cpa_tile<BM, 256>(sQL, g_Qlo, rowbase, tid);
    cpa_tile<BN, 128>(KH, g_Khi, grp * BN, ltid);
    cpa_tile<BN, 128>(KL, g_Klo, grp * BN, ltid);
    CPA_COMMIT();

    float O[32][4];
    #pragma unroll
    for (int dt = 0; dt < 32; ++dt) {
        O[dt][0] = 0.f; O[dt][1] = 0.f; O[dt][2] = 0.f; O[dt][3] = 0.f;
    }
    float m0 = -1e30f, m1 = -1e30f, l0 = 0.f, l1 = 0.f;

    const int rg0 = rowbase + 16 * wg + g;
    const int rg1 = rg0 + 8;
    const uint32_t* mrow0 = g_mask + (size_t)rg0 * (NN / 32);
    const uint32_t* mrow1 = g_mask + (size_t)rg1 * (NN / 32);

    const int qr = 16 * wg + (lane & 15);
    const int qcsel = lane >> 4;
    const int k_j_half = lane >> 4;
    const int k_kcsel = (lane >> 3) & 1;
    const int kr8 = lane & 7;
    const int v_dtsel = lane >> 4;
    const int vlane = lane & 15;

    const int NBLK = NN / BN;
    for (int i = 0; i < NBLK / 2; ++i) {
        const int b = 2 * i + grp;

        cpa_tile<BN, 128>(VS, g_V, b * BN, ltid);
        CPA_COMMIT();
        CPA_WAIT1();               // K[b] (and Q) landed
        GBAR(barid);

        // ---- S = Q K^T (16x32 per warp), fp16 x3 ----
        float S[4][4] = {};
        #pragma unroll 4
        for (int kk = 0; kk < 16; ++kk) {
            uint32_t aH[4], aL[4];
            ldm_x4(sQH + swz(qr, 2 * kk + qcsel), aH);
            ldm_x4(sQL + swz(qr, 2 * kk + qcsel), aL);
            #pragma unroll
            for (int jjp = 0; jjp < 2; ++jjp) {
                int krow = 8 * (2 * jjp + k_j_half) + kr8;
                int kc = 2 * kk + k_kcsel;
                uint32_t bH[4], bL[4];
                ldm_x4(KH + swz(krow, kc), bH);
                ldm_x4(KL + swz(krow, kc), bL);
                mma_f16(S[2 * jjp], aH, bH);
                mma_f16(S[2 * jjp], aL, bH);
                mma_f16(S[2 * jjp], aH, bL);
                mma_f16(S[2 * jjp + 1], aH, bH + 2);
                mma_f16(S[2 * jjp + 1], aL, bH + 2);
                mma_f16(S[2 * jjp + 1], aH, bL + 2);
            }
        }
        GBAR(barid);               // group done reading K[b]

        if (i + 1 < NBLK / 2) {
            cpa_tile<BN, 128>(KH, g_Khi, (b + 2) * BN, ltid);
            cpa_tile<BN, 128>(KL, g_Klo, (b + 2) * BN, ltid);
            CPA_COMMIT();
            CPA_WAIT1();           // V[b] landed (K still in flight)
        } else {
            CPA_WAIT0();
        }

        // ---- mask in place + row max ----
        const uint32_t mw0 = mrow0[b], mw1 = mrow1[b];
        float mt0 = -1e30f, mt1 = -1e30f;
        #pragma unroll
        for (int j = 0; j < 4; ++j)
            #pragma unroll
            for (int e = 0; e < 2; ++e) {
                int bit = 8 * j + 2 * t4 + e;
                S[j][e]     = ((mw0 >> bit) & 1u) ? S[j][e]     : -1e30f;
                S[j][2 + e] = ((mw1 >> bit) & 1u) ? S[j][2 + e] : -1e30f;
                mt0 = fmaxf(mt0, S[j][e]); mt1 = fmaxf(mt1, S[j][2 + e]);
            }
        mt0 = fmaxf(mt0, __shfl_xor_sync(0xffffffffu, mt0, 1));
        mt0 = fmaxf(mt0, __shfl_xor_sync(0xffffffffu, mt0, 2));
        mt1 = fmaxf(mt1, __shfl_xor_sync(0xffffffffu, mt1, 1));
        mt1 = fmaxf(mt1, __shfl_xor_sync(0xffffffffu, mt1, 2));

        const float mn0 = fmaxf(m0, mt0), mn1 = fmaxf(m1, mt1);
        const float sc0 = __expf(m0 - mn0), sc1 = __expf(m1 - mn1);

        // ---- exp (masked lanes underflow to exact 0) -> fp16 P frags ----
        uint32_t Ph[4][2];
        float rs0 = 0.f, rs1 = 0.f;
        #pragma unroll
        for (int j = 0; j < 4; ++j) {
            float p0 = __expf(S[j][0] - mn0), p1 = __expf(S[j][1] - mn0);
            float p2 = __expf(S[j][2] - mn1), p3 = __expf(S[j][3] - mn1);
            __half2 h01 = __floats2half2_rn(p0, p1);
            __half2 h23 = __floats2half2_rn(p2, p3);
            Ph[j][0] = *reinterpret_cast<uint32_t*>(&h01);
            Ph[j][1] = *reinterpret_cast<uint32_t*>(&h23);
            float2 f01 = __half22float2(h01), f23 = __half22float2(h23);
            rs0 += f01.x + f01.y;   // sum the ROUNDED p (matches PV numerator)
            rs1 += f23.x + f23.y;
        }
        rs0 += __shfl_xor_sync(0xffffffffu, rs0, 1);
        rs0 += __shfl_xor_sync(0xffffffffu, rs0, 2);
        rs1 += __shfl_xor_sync(0xffffffffu, rs1, 1);
        rs1 += __shfl_xor_sync(0xffffffffu, rs1, 2);
        l0 = l0 * sc0 + rs0;
        l1 = l1 * sc1 + rs1;
        m0 = mn0; m1 = mn1;

        if (__ballot_sync(0xffffffffu, (sc0 != 1.f) || (sc1 != 1.f))) {
            #pragma unroll
            for (int dt = 0; dt < 32; ++dt) {
                O[dt][0] *= sc0; O[dt][1] *= sc0;
                O[dt][2] *= sc1; O[dt][3] *= sc1;
            }
        }

        GBAR(barid);               // V[b] visible to whole group

        // ---- O += P V (single product, x4 trans) ----
        #pragma unroll
        for (int kp = 0; kp < 2; ++kp) {
            uint32_t aH[4] = {Ph[2 * kp][0], Ph[2 * kp][1], Ph[2 * kp + 1][0], Ph[2 * kp + 1][1]};
            const int vr = 16 * kp + vlane;
            #pragma unroll
            for (int dtp = 0; dtp < 16; ++dtp) {
                uint32_t bV[4];
                ldm_x4t(VS + swz(vr, 2 * dtp + v_dtsel), bV);
                mma_f16(O[2 * dtp], aH, bV);
                mma_f16(O[2 * dtp + 1], aH, bV + 2);
            }
        }
        GBAR(barid);               // group done reading V[b]
    }

    // ---- merge groups ----
    __syncthreads();
    float* Os = reinterpret_cast<float*>(smem + 65536);   // [64][264] padded
    float* ml = reinterpret_cast<float*>(smem + 133120);  // m[64], l[64]
    const int r0l = 16 * wg + g, r1l = r0l + 8;
    if (grp == 1) {
        #pragma unroll
        for (int dt = 0; dt < 32; ++dt) {
            int c = 8 * dt + 2 * t4;
            Os[r0l * 264 + c] = O[dt][0]; Os[r0l * 264 + c + 1] = O[dt][1];
            Os[r1l * 264 + c] = O[dt][2]; Os[r1l * 264 + c + 1] = O[dt][3];
        }
        if (t4 == 0) {
            ml[r0l] = m0; ml[64 + r0l] = l0;
            ml[r1l] = m1; ml[64 + r1l] = l1;
        }
    }
    __syncthreads();
    if (grp == 0) {
        float mo0 = ml[r0l], lo0 = ml[64 + r0l];
        float mo1 = ml[r1l], lo1 = ml[64 + r1l];
        float mm0 = fmaxf(m0, mo0), mm1 = fmaxf(m1, mo1);
        float wa0 = __expf(m0 - mm0), wb0 = __expf(mo0 - mm0);
        float wa1 = __expf(m1 - mm1), wb1 = __expf(mo1 - mm1);
        float inv0 = 1.f / (l0 * wa0 + lo0 * wb0);
        float inv1 = 1.f / (l1 * wa1 + lo1 * wb1);
        float2* o0 = reinterpret_cast<float2*>(Out + (size_t)rg0 * DD);
        float2* o1 = reinterpret_cast<float2*>(Out + (size_t)rg1 * DD);
        #pragma unroll
        for (int dt = 0; dt < 32; ++dt) {
            int c = 8 * dt + 2 * t4;
            o0[4 * dt + t4] = make_float2(
                (O[dt][0] * wa0 + Os[r0l * 264 + c] * wb0) * inv0,
                (O[dt][1] * wa0 + Os[r0l * 264 + c + 1] * wb0) * inv0);
            o1[4 * dt + t4] = make_float2(
                (O[dt][2] * wa1 + Os[r1l * 264 + c] * wb1) * inv1,
                (O[dt][3] * wa1 + Os[r1l * 264 + c + 1] * wb1) * inv1);
        }
    }
}

// ---------------------------------------------------------------------------
extern "C" void kernel_launch(void* const* d_in, const int* in_sizes, int n_in,
                              void* d_out, int out_size) {
    const float* X  = (const float*)d_in[0];
    const int*   A  = (const int*)d_in[1];
    const float* Wq = (const float*)d_in[2];
    const float* Wk = (const float*)d_in[3];
    const float* Wv = (const float*)d_in[4];
    float* Out = (float*)d_out;

    static int attr_set = 0;
    const int smem_attn = 163840;
    const int smem_qkv = 196608;
    if (!attr_set) {
        cudaFuncSetAttribute(attn_kernel, cudaFuncAttributeMaxDynamicSharedMemorySize,
                             smem_attn);
        cudaFuncSetAttribute(qkv_mma_kernel, cudaFuncAttributeMaxDynamicSharedMemorySize,
                             smem_qkv);
        attr_set = 1;
    }

    pack_mask_kernel<<<NN, 256>>>(A);
    split_kernel<<<2048 + 768, 256>>>(X, Wq, Wk, Wv);
    qkv_mma_kernel<<<dim3(NN / 64, 2, 3), 256, smem_qkv>>>();
    attn_kernel<<<NN / BM, 256, smem_attn>>>(Out);
}